// round 1
// baseline (speedup 1.0000x reference)
#include <cuda_runtime.h>
#include <math.h>
#include <stdint.h>

#define BB 16
#define TT 600
#define VV 20000
#define EE 300
#define HH 512
#define BT (BB*TT)   // 9600

// ---------------- scratch (__device__ globals: no allocation) ----------------
__device__ float g_P[(size_t)BT*1024];   // [9600][1024]: cols 0..511 = enc@aw2g, 512..1023 = enc@aw2c
__device__ float g_z1[BB*2048];
__device__ float g_z2[BB*2048];
__device__ float g_q[BB*1024];           // cols 0..511 = h2n@aw1g, 512..1023 = h2n@aw1c
__device__ float g_sg[BB*TT];
__device__ float g_sc[BB*TT];
__device__ float g_alignc[BB*TT];
__device__ float g_ctx[BB*HH];
__device__ float g_logits[(size_t)BB*VV];
__device__ float g_vred[BB*2];
__device__ float g_switch[BB];

__device__ __forceinline__ float sigf(float x){ return 1.0f/(1.0f+expf(-x)); }

// ---------------- big SGEMM: C[9600,1024] = enc_outs[9600,512] @ [aw2g | aw2c] ----------------
__global__ void sgemm_attn_kernel(const float* __restrict__ A,
                                  const float* __restrict__ Wg,
                                  const float* __restrict__ Wc) {
  __shared__ float As[16][132];
  __shared__ float Bs[16][64];
  int tid = threadIdx.x;                 // 256
  int bm = blockIdx.x * 128;             // 75 blocks
  int bn = blockIdx.y * 64;              // 16 blocks
  const float* W = (bn < 512) ? Wg : Wc;
  int wc0 = bn & 511;
  int tm = tid >> 4, tn = tid & 15;
  float acc[8][4];
  #pragma unroll
  for (int i=0;i<8;i++)
    #pragma unroll
    for (int j=0;j<4;j++) acc[i][j]=0.f;

  for (int kc=0; kc<512; kc+=16) {
    #pragma unroll
    for (int i=0;i<2;i++){
      int id = tid + i*256;
      int row = id >> 2;
      int k4 = (id & 3) << 2;
      float4 av = *(const float4*)&A[(size_t)(bm+row)*512 + kc + k4];
      As[k4+0][row]=av.x; As[k4+1][row]=av.y; As[k4+2][row]=av.z; As[k4+3][row]=av.w;
    }
    {
      int kb = tid >> 4;
      int cc = (tid & 15) << 2;
      *(float4*)&Bs[kb][cc] = *(const float4*)&W[(size_t)(kc+kb)*512 + wc0 + cc];
    }
    __syncthreads();
    #pragma unroll
    for (int k=0;k<16;k++){
      float4 a0 = *(const float4*)&As[k][tm*8];
      float4 a1 = *(const float4*)&As[k][tm*8+4];
      float4 bv = *(const float4*)&Bs[k][tn*4];
      float am[8] = {a0.x,a0.y,a0.z,a0.w,a1.x,a1.y,a1.z,a1.w};
      float bm2[4] = {bv.x,bv.y,bv.z,bv.w};
      #pragma unroll
      for (int i=0;i<8;i++)
        #pragma unroll
        for (int j=0;j<4;j++)
          acc[i][j] = fmaf(am[i], bm2[j], acc[i][j]);
    }
    __syncthreads();
  }
  #pragma unroll
  for (int i=0;i<8;i++){
    float4 o = make_float4(acc[i][0],acc[i][1],acc[i][2],acc[i][3]);
    *(float4*)&g_P[(size_t)(bm + tm*8 + i)*1024 + bn + tn*4] = o;
  }
}

// ---------------- generic small-M (M=16) GEMM: C[16,N] = A[16,K] @ W[K,N] ----------------
struct GArgs {
  const float* A0; const float* A1;
  const float* W0; const float* W1;
  const float* bias;
  const int* xidx; const float* emb;
  float* C;
  int K; int N;
};

enum { V_Z1=0, V_Z2=1, V_Q=2, V_HA=3, V_LOG=4 };

template<int VAR>
__device__ __forceinline__ float loadA(const GArgs& g, int b, int k) {
  if (VAR==V_Z1) {
    if (k < 300) return g.emb[(size_t)g.xidx[b]*300 + k];   // embedding gather
    if (k < 812) return g.A0[b*512 + (k-300)];              // last_hidden_attn
    return g.A1[b*512 + (k-812)];                           // h1
  }
  if (VAR==V_Z2 || VAR==V_HA) {
    if (k < 512) return g.A0[b*512+k];
    return g.A1[b*512 + (k-512)];
  }
  return g.A0[b*512+k]; // V_Q, V_LOG
}

template<int VAR>
__device__ __forceinline__ float loadW(const GArgs& g, int k, int c) {
  if (VAR==V_Z1) return (k<812) ? g.W0[(size_t)k*2048+c] : g.W1[(size_t)(k-812)*2048+c];
  if (VAR==V_Z2) return (k<512) ? g.W0[(size_t)k*2048+c] : g.W1[(size_t)(k-512)*2048+c];
  if (VAR==V_Q)  return (c<512) ? g.W0[(size_t)k*512+c]  : g.W1[(size_t)k*512+(c-512)];
  if (VAR==V_HA) return g.W0[(size_t)k*512+c];
  return g.W0[(size_t)k*VV+c];  // V_LOG
}

template<int VAR>
__global__ void gemm16_kernel(GArgs g) {
  __shared__ float As[64][16];       // [k_local][b]
  __shared__ float red[4][16][65];
  int tid = threadIdx.x;             // 256
  int c2 = tid & 63;
  int slice = tid >> 6;              // 0..3 (k-slice)
  int col = blockIdx.x*64 + c2;
  bool colok = col < g.N;
  float acc[16];
  #pragma unroll
  for (int b=0;b<16;b++) acc[b]=0.f;

  int nch = (g.K + 63) >> 6;
  for (int ch=0; ch<nch; ch++) {
    int kc = ch*64;
    __syncthreads();
    #pragma unroll
    for (int i=0;i<4;i++) {
      int e = tid + i*256;
      int b = e >> 6, kl = e & 63;
      int k = kc + kl;
      As[kl][b] = (k < g.K) ? loadA<VAR>(g, b, k) : 0.f;
    }
    __syncthreads();
    if (colok) {
      #pragma unroll
      for (int kk=0; kk<16; kk++) {
        int kl = slice*16+kk;
        int k = kc + kl;
        float w = (k < g.K) ? loadW<VAR>(g, k, col) : 0.f;
        const float4* ap = (const float4*)(&As[kl][0]);
        float4 v0 = ap[0], v1 = ap[1], v2 = ap[2], v3 = ap[3];
        acc[0]  = fmaf(v0.x,w,acc[0]);  acc[1]  = fmaf(v0.y,w,acc[1]);
        acc[2]  = fmaf(v0.z,w,acc[2]);  acc[3]  = fmaf(v0.w,w,acc[3]);
        acc[4]  = fmaf(v1.x,w,acc[4]);  acc[5]  = fmaf(v1.y,w,acc[5]);
        acc[6]  = fmaf(v1.z,w,acc[6]);  acc[7]  = fmaf(v1.w,w,acc[7]);
        acc[8]  = fmaf(v2.x,w,acc[8]);  acc[9]  = fmaf(v2.y,w,acc[9]);
        acc[10] = fmaf(v2.z,w,acc[10]); acc[11] = fmaf(v2.w,w,acc[11]);
        acc[12] = fmaf(v3.x,w,acc[12]); acc[13] = fmaf(v3.y,w,acc[13]);
        acc[14] = fmaf(v3.z,w,acc[14]); acc[15] = fmaf(v3.w,w,acc[15]);
      }
    }
  }
  __syncthreads();
  #pragma unroll
  for (int b=0;b<16;b++) red[slice][b][c2] = acc[b];
  __syncthreads();
  if (colok) {
    #pragma unroll
    for (int i=0;i<4;i++) {
      int b = slice*4+i;
      float v = red[0][b][c2]+red[1][b][c2]+red[2][b][c2]+red[3][b][c2];
      if (g.bias) v += g.bias[col];
      if (VAR==V_HA) v = tanhf(v);
      g.C[(size_t)b*g.N + col] = v;
    }
  }
}

// ---------------- LSTM pointwise ----------------
__global__ void lstm_pw_kernel(const float* __restrict__ z, const float* __restrict__ cin,
                               float* __restrict__ hout, float* __restrict__ cout) {
  int idx = blockIdx.x*blockDim.x + threadIdx.x;
  if (idx >= BB*HH) return;
  int b = idx >> 9, j = idx & 511;
  const float* zb = z + b*2048;
  float iv = sigf(zb[j]);
  float fv = sigf(zb[512+j]);
  float gv = tanhf(zb[1024+j]);
  float ov = sigf(zb[1536+j]);
  float c = fv*cin[idx] + iv*gv;
  hout[idx] = ov*tanhf(c);
  cout[idx] = c;
}

// ---------------- attention scores: both heads fused ----------------
__global__ void scores_kernel(const float* __restrict__ avg, const float* __restrict__ avc) {
  int r = blockIdx.x;            // 0..9599 = b*600+t
  int b = r / TT;
  int tid = threadIdx.x;         // 256
  const float* prow = g_P + (size_t)r*1024;
  const float* qb = g_q + b*1024;
  float ag=0.f, ac=0.f;
  for (int j=tid; j<512; j+=256) {
    ag += tanhf(qb[j]     + prow[j])     * avg[j];
    ac += tanhf(qb[512+j] + prow[512+j]) * avc[j];
  }
  #pragma unroll
  for (int o=16;o>0;o>>=1){
    ag += __shfl_down_sync(0xffffffffu, ag, o);
    ac += __shfl_down_sync(0xffffffffu, ac, o);
  }
  __shared__ float rg[8], rc[8];
  int w = tid>>5, l = tid&31;
  if (l==0){ rg[w]=ag; rc[w]=ac; }
  __syncthreads();
  if (tid==0){
    float sg=0.f, sc=0.f;
    #pragma unroll
    for (int i=0;i<8;i++){ sg+=rg[i]; sc+=rc[i]; }
    g_sg[r]=sg; g_sc[r]=sc;
  }
}

// ---------------- softmax over T (both heads) + context (head g) ----------------
__global__ void softmax_ctx_kernel(const float* __restrict__ enc) {
  int b = blockIdx.x, tid = threadIdx.x;   // 512 threads
  __shared__ float ag[TT], ac[TT];
  __shared__ float rbuf[512];
  for (int t=tid;t<TT;t+=512){ ag[t]=g_sg[b*TT+t]; ac[t]=g_sc[b*TT+t]; }
  __syncthreads();
  for (int pass=0; pass<2; pass++) {
    float* arr = pass ? ac : ag;
    float mx = -1e30f;
    for (int t=tid;t<TT;t+=512) mx = fmaxf(mx, arr[t]);
    rbuf[tid]=mx; __syncthreads();
    for (int s=256;s>0;s>>=1){ if (tid<s) rbuf[tid]=fmaxf(rbuf[tid],rbuf[tid+s]); __syncthreads(); }
    mx = rbuf[0]; __syncthreads();
    float ls=0.f;
    for (int t=tid;t<TT;t+=512){ float e=expf(arr[t]-mx); arr[t]=e; ls+=e; }
    rbuf[tid]=ls; __syncthreads();
    for (int s=256;s>0;s>>=1){ if (tid<s) rbuf[tid]+=rbuf[tid+s]; __syncthreads(); }
    float inv = 1.0f/rbuf[0]; __syncthreads();
    for (int t=tid;t<TT;t+=512) arr[t]*=inv;
    __syncthreads();
  }
  for (int t=tid;t<TT;t+=512) g_alignc[b*TT+t]=ac[t];
  // context = align_g @ enc_outs[b]
  const float* eb = enc + (size_t)b*TT*HH + tid;
  float a0=0.f,a1=0.f,a2=0.f,a3=0.f;
  for (int t=0;t<TT;t+=4){
    a0 += ag[t]  *eb[(size_t)(t  )*HH];
    a1 += ag[t+1]*eb[(size_t)(t+1)*HH];
    a2 += ag[t+2]*eb[(size_t)(t+2)*HH];
    a3 += ag[t+3]*eb[(size_t)(t+3)*HH];
  }
  g_ctx[b*HH+tid] = (a0+a1)+(a2+a3);
}

// ---------------- switch = sigmoid(ha @ Wf + bf) ----------------
__global__ void switch_kernel(const float* __restrict__ ha, const float* __restrict__ Wf,
                              const float* __restrict__ bf) {
  int b = blockIdx.x, tid = threadIdx.x;   // 512
  __shared__ float rb[512];
  rb[tid] = ha[b*HH+tid]*Wf[tid];
  __syncthreads();
  for (int s=256;s>0;s>>=1){ if (tid<s) rb[tid]+=rb[tid+s]; __syncthreads(); }
  if (tid==0) g_switch[b] = sigf(rb[0]+bf[0]);
}

// ---------------- vocab softmax reductions (max, sumexp) ----------------
__global__ void vred_kernel() {
  int b = blockIdx.x, tid = threadIdx.x;   // 1024
  __shared__ float rb[1024];
  const float* lb = g_logits + (size_t)b*VV;
  float mx = -1e30f;
  for (int i=tid;i<VV;i+=1024) mx = fmaxf(mx, lb[i]);
  rb[tid]=mx; __syncthreads();
  for (int s=512;s>0;s>>=1){ if (tid<s) rb[tid]=fmaxf(rb[tid],rb[tid+s]); __syncthreads(); }
  mx = rb[0]; __syncthreads();
  float sm=0.f;
  for (int i=tid;i<VV;i+=1024) sm += expf(lb[i]-mx);
  rb[tid]=sm; __syncthreads();
  for (int s=512;s>0;s>>=1){ if (tid<s) rb[tid]+=rb[tid+s]; __syncthreads(); }
  if (tid==0){ g_vred[b*2]=mx; g_vred[b*2+1]=rb[0]; }
}

// ---------------- final: copy_prob (768MB stream) + mix with gen_prob ----------------
__global__ void final_kernel(const float* __restrict__ enc_ins, float* __restrict__ result) {
  int b = blockIdx.y, tid = threadIdx.x;   // 256
  int v = blockIdx.x*256 + tid;
  __shared__ float ac[TT];
  for (int t=tid;t<TT;t+=256) ac[t]=g_alignc[b*TT+t];
  __syncthreads();
  if (v >= VV) return;
  const float* eb = enc_ins + (size_t)b*TT*VV + v;
  float a0=0.f,a1=0.f,a2=0.f,a3=0.f;
  for (int t=0;t<TT;t+=4){
    a0 += ac[t]  * eb[(size_t)(t  )*VV];
    a1 += ac[t+1]* eb[(size_t)(t+1)*VV];
    a2 += ac[t+2]* eb[(size_t)(t+2)*VV];
    a3 += ac[t+3]* eb[(size_t)(t+3)*VV];
  }
  float copy = (a0+a1)+(a2+a3);
  float sw = g_switch[b];
  float mx = g_vred[b*2], sm = g_vred[b*2+1];
  float gen = expf(g_logits[(size_t)b*VV+v]-mx)/sm;
  result[(size_t)b*VV+v] = gen*(1.0f-sw) + copy*sw;
}

// ---------------- launch ----------------
extern "C" void kernel_launch(void* const* d_in, const int* in_sizes, int n_in,
                              void* d_out, int out_size) {
  const int*   x        = (const int*)  d_in[0];
  const float* lha      = (const float*)d_in[1];
  const float* h1       = (const float*)d_in[2];
  const float* c1       = (const float*)d_in[3];
  const float* h2       = (const float*)d_in[4];
  const float* c2       = (const float*)d_in[5];
  const float* enc_outs = (const float*)d_in[6];
  const float* enc_ins  = (const float*)d_in[7];
  const float* emb      = (const float*)d_in[8];
  const float* k1       = (const float*)d_in[9];
  const float* r1       = (const float*)d_in[10];
  const float* b1       = (const float*)d_in[11];
  const float* k2       = (const float*)d_in[12];
  const float* r2       = (const float*)d_in[13];
  const float* b2       = (const float*)d_in[14];
  const float* Wh       = (const float*)d_in[15];
  const float* bh       = (const float*)d_in[16];
  const float* Wg       = (const float*)d_in[17];
  const float* bg       = (const float*)d_in[18];
  const float* Wf       = (const float*)d_in[19];
  const float* bf       = (const float*)d_in[20];
  const float* aw1g     = (const float*)d_in[21];
  const float* aw2g     = (const float*)d_in[22];
  const float* avg      = (const float*)d_in[23];
  const float* aw1c     = (const float*)d_in[24];
  const float* aw2c     = (const float*)d_in[25];
  const float* avc      = (const float*)d_in[26];

  float* out = (float*)d_out;
  float* out_result = out;                       // 16*20000
  float* out_hidden = out + BB*VV;               // 16*512
  float* out_h1n    = out_hidden + BB*HH;
  float* out_c1n    = out_h1n + BB*HH;
  float* out_h2n    = out_c1n + BB*HH;
  float* out_c2n    = out_h2n + BB*HH;

  float *p_z1, *p_z2, *p_q, *p_ctx, *p_logits;
  cudaGetSymbolAddress((void**)&p_z1, g_z1);
  cudaGetSymbolAddress((void**)&p_z2, g_z2);
  cudaGetSymbolAddress((void**)&p_q, g_q);
  cudaGetSymbolAddress((void**)&p_ctx, g_ctx);
  cudaGetSymbolAddress((void**)&p_logits, g_logits);

  // Big independent GEMM first: P = enc_outs @ [aw2g | aw2c]
  sgemm_attn_kernel<<<dim3(75,16), 256>>>(enc_outs, aw2g, aw2c);

  // LSTM 1
  GArgs az1; az1.A0=lha; az1.A1=h1; az1.W0=k1; az1.W1=r1; az1.bias=b1;
  az1.xidx=x; az1.emb=emb; az1.C=p_z1; az1.K=1324; az1.N=2048;
  gemm16_kernel<V_Z1><<<32,256>>>(az1);
  lstm_pw_kernel<<<32,256>>>(p_z1, c1, out_h1n, out_c1n);

  // LSTM 2
  GArgs az2; az2.A0=out_h1n; az2.A1=h2; az2.W0=k2; az2.W1=r2; az2.bias=b2;
  az2.xidx=nullptr; az2.emb=nullptr; az2.C=p_z2; az2.K=1024; az2.N=2048;
  gemm16_kernel<V_Z2><<<32,256>>>(az2);
  lstm_pw_kernel<<<32,256>>>(p_z2, c2, out_h2n, out_c2n);

  // queries for both attention heads
  GArgs aq; aq.A0=out_h2n; aq.A1=nullptr; aq.W0=aw1g; aq.W1=aw1c; aq.bias=nullptr;
  aq.xidx=nullptr; aq.emb=nullptr; aq.C=p_q; aq.K=512; aq.N=1024;
  gemm16_kernel<V_Q><<<16,256>>>(aq);

  // scores, softmax + context + align_c
  scores_kernel<<<BT,256>>>(avg, avc);
  softmax_ctx_kernel<<<BB,512>>>(enc_outs);

  // hidden_att = tanh([ctx, h2n] @ Wh + bh)
  GArgs aha; aha.A0=p_ctx; aha.A1=out_h2n; aha.W0=Wh; aha.W1=nullptr; aha.bias=bh;
  aha.xidx=nullptr; aha.emb=nullptr; aha.C=out_hidden; aha.K=1024; aha.N=512;
  gemm16_kernel<V_HA><<<8,256>>>(aha);

  switch_kernel<<<BB,512>>>(out_hidden, Wf, bf);

  // gen logits
  GArgs alog; alog.A0=out_hidden; alog.A1=nullptr; alog.W0=Wg; alog.W1=nullptr; alog.bias=bg;
  alog.xidx=nullptr; alog.emb=nullptr; alog.C=p_logits; alog.K=512; alog.N=VV;
  gemm16_kernel<V_LOG><<<(VV+63)/64,256>>>(alog);

  vred_kernel<<<BB,1024>>>();

  // copy pass + final mix
  final_kernel<<<dim3((VV+255)/256, BB), 256>>>(enc_ins, out_result);
}

// round 2
// speedup vs baseline: 1.5392x; 1.5392x over previous
#include <cuda_runtime.h>
#include <math.h>
#include <stdint.h>

#define BB 16
#define TT 600
#define VV 20000
#define EE 300
#define HH 512
#define BT (BB*TT)   // 9600

// ---------------- scratch ----------------
__device__ float g_P[(size_t)BT*1024];   // [9600][1024]: 0..511 = enc@aw2g, 512..1023 = enc@aw2c
__device__ float g_z1[BB*2048];
__device__ float g_z2[BB*2048];
__device__ float g_q[BB*1024];
__device__ float g_ha[BB*HH];
__device__ float g_sg[BB*TT];
__device__ float g_sc[BB*TT];
__device__ float g_aligng[BB*TT];
__device__ float g_alignc[BB*TT];
__device__ float g_ctx[BB*HH];
__device__ float g_logits[(size_t)BB*VV];
__device__ float g_vred[BB*2];
__device__ float g_switch[BB];

__device__ __forceinline__ float sigf(float x){ return 1.0f/(1.0f+expf(-x)); }

// ---------------- init: write biases / zeros into accumulators ----------------
__global__ void init_kernel(const float* __restrict__ b1, const float* __restrict__ b2,
                            const float* __restrict__ bh) {
  int idx = blockIdx.x*blockDim.x + threadIdx.x;
  // layout: [0,32768) z1 | [32768,65536) z2 | [65536,81920) q | [81920,90112) ha | [90112,98304) ctx
  if (idx < 32768)            g_z1[idx] = b1[idx & 2047];
  else if (idx < 65536)       g_z2[idx-32768] = b2[idx & 2047];
  else if (idx < 81920)       g_q[idx-65536] = 0.f;
  else if (idx < 90112)       g_ha[idx-81920] = bh[idx & 511];
  else if (idx < 98304)       g_ctx[idx-90112] = 0.f;
}

// ---------------- big SGEMM: g_P[9600,1024] = enc_outs[9600,512] @ [aw2g | aw2c] ----------------
// 128x128 tile, 256 threads, 8x8 per thread
__global__ void sgemm_attn_kernel(const float* __restrict__ A,
                                  const float* __restrict__ Wg,
                                  const float* __restrict__ Wc) {
  __shared__ __align__(16) float As[16][132];
  __shared__ __align__(16) float Bs[16][128];
  int tid = threadIdx.x;                 // 256
  int bm = blockIdx.x * 128;             // 75
  int bn = blockIdx.y * 128;             // 8
  const float* W = (bn < 512) ? Wg : Wc;
  int wc0 = bn & 511;
  int tm = tid >> 4, tn = tid & 15;
  float acc[8][8];
  #pragma unroll
  for (int i=0;i<8;i++)
    #pragma unroll
    for (int j=0;j<8;j++) acc[i][j]=0.f;

  for (int kc=0; kc<512; kc+=16) {
    #pragma unroll
    for (int i=0;i<2;i++){
      int f = tid*2 + i;                  // 0..511 float4s of A-chunk
      int row = f >> 2;
      int kq  = (f & 3) << 2;
      float4 av = *(const float4*)&A[(size_t)(bm+row)*512 + kc + kq];
      As[kq+0][row]=av.x; As[kq+1][row]=av.y; As[kq+2][row]=av.z; As[kq+3][row]=av.w;
    }
    #pragma unroll
    for (int i=0;i<2;i++){
      int f = tid*2 + i;                  // 0..511 float4s of B-chunk
      int kb = f >> 5;
      int c4 = (f & 31) << 2;
      *(float4*)&Bs[kb][c4] = *(const float4*)&W[(size_t)(kc+kb)*512 + wc0 + c4];
    }
    __syncthreads();
    #pragma unroll
    for (int k=0;k<16;k++){
      float4 a0 = *(const float4*)&As[k][tm*8];
      float4 a1 = *(const float4*)&As[k][tm*8+4];
      float4 b0 = *(const float4*)&Bs[k][tn*8];
      float4 b1 = *(const float4*)&Bs[k][tn*8+4];
      float am[8] = {a0.x,a0.y,a0.z,a0.w,a1.x,a1.y,a1.z,a1.w};
      float bv[8] = {b0.x,b0.y,b0.z,b0.w,b1.x,b1.y,b1.z,b1.w};
      #pragma unroll
      for (int i=0;i<8;i++)
        #pragma unroll
        for (int j=0;j<8;j++)
          acc[i][j] = fmaf(am[i], bv[j], acc[i][j]);
    }
    __syncthreads();
  }
  #pragma unroll
  for (int i=0;i<8;i++){
    float* orow = &g_P[(size_t)(bm + tm*8 + i)*1024 + bn + tn*8];
    *(float4*)&orow[0] = make_float4(acc[i][0],acc[i][1],acc[i][2],acc[i][3]);
    *(float4*)&orow[4] = make_float4(acc[i][4],acc[i][5],acc[i][6],acc[i][7]);
  }
}

// ---------------- small-M GEMM, K-split + atomic accumulate ----------------
struct GArgs {
  const float* A0; const float* A1;
  const float* W0; const float* W1;
  const int* xidx; const float* emb;
  float* C;
  int K; int N;
};

enum { V_Z1=0, V_Z2=1, V_Q=2, V_HA=3 };

template<int VAR>
__device__ __forceinline__ float loadA(const GArgs& g, int b, int k) {
  if (VAR==V_Z1) {
    if (k < 300) return g.emb[(size_t)g.xidx[b]*300 + k];
    if (k < 812) return g.A0[b*512 + (k-300)];
    return g.A1[b*512 + (k-812)];
  }
  if (VAR==V_Z2 || VAR==V_HA) {
    if (k < 512) return g.A0[b*512+k];
    return g.A1[b*512 + (k-512)];
  }
  return g.A0[b*512+k]; // V_Q
}

template<int VAR>
__device__ __forceinline__ float loadW(const GArgs& g, int k, int c) {
  if (VAR==V_Z1) return (k<812) ? g.W0[(size_t)k*2048+c] : g.W1[(size_t)(k-812)*2048+c];
  if (VAR==V_Z2) return (k<512) ? g.W0[(size_t)k*2048+c] : g.W1[(size_t)(k-512)*2048+c];
  if (VAR==V_Q)  return (c<512) ? g.W0[(size_t)k*512+c]  : g.W1[(size_t)k*512+(c-512)];
  return g.W0[(size_t)k*512+c]; // V_HA
}

// grid: (N/128, ceil(K/64)); block: 128. One column per thread.
template<int VAR>
__global__ void gemm16_atomic(GArgs g) {
  __shared__ __align__(16) float As[64][16];
  int tid = threadIdx.x;                 // 128
  int col = blockIdx.x*128 + tid;
  int k0  = blockIdx.y*64;

  #pragma unroll
  for (int i=0;i<8;i++) {
    int e = tid + i*128;                 // 0..1023
    int kl = e >> 4, b = e & 15;
    int k = k0 + kl;
    As[kl][b] = (k < g.K) ? loadA<VAR>(g, b, k) : 0.f;
  }
  __syncthreads();

  float acc[16];
  #pragma unroll
  for (int b=0;b<16;b++) acc[b]=0.f;

  #pragma unroll 4
  for (int kl=0; kl<64; kl++) {
    int k = k0 + kl;
    float w = (k < g.K) ? loadW<VAR>(g, k, col) : 0.f;
    const float4* ap = (const float4*)&As[kl][0];
    float4 v0 = ap[0], v1 = ap[1], v2 = ap[2], v3 = ap[3];
    acc[0]  = fmaf(v0.x,w,acc[0]);  acc[1]  = fmaf(v0.y,w,acc[1]);
    acc[2]  = fmaf(v0.z,w,acc[2]);  acc[3]  = fmaf(v0.w,w,acc[3]);
    acc[4]  = fmaf(v1.x,w,acc[4]);  acc[5]  = fmaf(v1.y,w,acc[5]);
    acc[6]  = fmaf(v1.z,w,acc[6]);  acc[7]  = fmaf(v1.w,w,acc[7]);
    acc[8]  = fmaf(v2.x,w,acc[8]);  acc[9]  = fmaf(v2.y,w,acc[9]);
    acc[10] = fmaf(v2.z,w,acc[10]); acc[11] = fmaf(v2.w,w,acc[11]);
    acc[12] = fmaf(v3.x,w,acc[12]); acc[13] = fmaf(v3.y,w,acc[13]);
    acc[14] = fmaf(v3.z,w,acc[14]); acc[15] = fmaf(v3.w,w,acc[15]);
  }
  #pragma unroll
  for (int b=0;b<16;b++)
    atomicAdd(&g.C[(size_t)b*g.N + col], acc[b]);
}

// ---------------- logits: C[16,20000] = ha[16,512] @ Wg + bg (direct write) ----------------
__global__ void gemm16_logits(const float* __restrict__ A, const float* __restrict__ W,
                              const float* __restrict__ bias) {
  __shared__ __align__(16) float As[512][16];   // 32 KB
  int tid = threadIdx.x;                 // 128
  int col = blockIdx.x*128 + tid;
  #pragma unroll
  for (int i=0;i<64;i++) {
    int e = tid + i*128;                 // 0..8191
    int kl = e >> 4, b = e & 15;
    As[kl][b] = A[b*512 + kl];
  }
  __syncthreads();
  if (col >= VV) return;
  float acc[16];
  #pragma unroll
  for (int b=0;b<16;b++) acc[b]=0.f;
  #pragma unroll 4
  for (int k=0; k<512; k++) {
    float w = W[(size_t)k*VV + col];
    const float4* ap = (const float4*)&As[k][0];
    float4 v0 = ap[0], v1 = ap[1], v2 = ap[2], v3 = ap[3];
    acc[0]  = fmaf(v0.x,w,acc[0]);  acc[1]  = fmaf(v0.y,w,acc[1]);
    acc[2]  = fmaf(v0.z,w,acc[2]);  acc[3]  = fmaf(v0.w,w,acc[3]);
    acc[4]  = fmaf(v1.x,w,acc[4]);  acc[5]  = fmaf(v1.y,w,acc[5]);
    acc[6]  = fmaf(v1.z,w,acc[6]);  acc[7]  = fmaf(v1.w,w,acc[7]);
    acc[8]  = fmaf(v2.x,w,acc[8]);  acc[9]  = fmaf(v2.y,w,acc[9]);
    acc[10] = fmaf(v2.z,w,acc[10]); acc[11] = fmaf(v2.w,w,acc[11]);
    acc[12] = fmaf(v3.x,w,acc[12]); acc[13] = fmaf(v3.y,w,acc[13]);
    acc[14] = fmaf(v3.z,w,acc[14]); acc[15] = fmaf(v3.w,w,acc[15]);
  }
  float bv = bias[col];
  #pragma unroll
  for (int b=0;b<16;b++)
    g_logits[(size_t)b*VV + col] = acc[b] + bv;
}

// ---------------- LSTM pointwise ----------------
__global__ void lstm_pw_kernel(const float* __restrict__ z, const float* __restrict__ cin,
                               float* __restrict__ hout, float* __restrict__ cout) {
  int idx = blockIdx.x*blockDim.x + threadIdx.x;
  if (idx >= BB*HH) return;
  int b = idx >> 9, j = idx & 511;
  const float* zb = z + b*2048;
  float iv = sigf(zb[j]);
  float fv = sigf(zb[512+j]);
  float gv = tanhf(zb[1024+j]);
  float ov = sigf(zb[1536+j]);
  float c = fv*cin[idx] + iv*gv;
  hout[idx] = ov*tanhf(c);
  cout[idx] = c;
}

// ---------------- attention scores ----------------
__global__ void scores_kernel(const float* __restrict__ avg, const float* __restrict__ avc) {
  int r = blockIdx.x;            // 0..9599
  int b = r / TT;
  int tid = threadIdx.x;         // 256
  const float* prow = g_P + (size_t)r*1024;
  const float* qb = g_q + b*1024;
  float ag=0.f, ac=0.f;
  for (int j=tid; j<512; j+=256) {
    ag += tanhf(qb[j]     + prow[j])     * avg[j];
    ac += tanhf(qb[512+j] + prow[512+j]) * avc[j];
  }
  #pragma unroll
  for (int o=16;o>0;o>>=1){
    ag += __shfl_down_sync(0xffffffffu, ag, o);
    ac += __shfl_down_sync(0xffffffffu, ac, o);
  }
  __shared__ float rg[8], rc[8];
  int w = tid>>5, l = tid&31;
  if (l==0){ rg[w]=ag; rc[w]=ac; }
  __syncthreads();
  if (tid==0){
    float sg=0.f, sc=0.f;
    #pragma unroll
    for (int i=0;i<8;i++){ sg+=rg[i]; sc+=rc[i]; }
    g_sg[r]=sg; g_sc[r]=sc;
  }
}

// ---------------- softmax over T (both heads) ----------------
__global__ void softmax_kernel() {
  int b = blockIdx.x, tid = threadIdx.x;   // 256
  __shared__ float ag[TT], ac[TT];
  __shared__ float rbuf[256];
  for (int t=tid;t<TT;t+=256){ ag[t]=g_sg[b*TT+t]; ac[t]=g_sc[b*TT+t]; }
  __syncthreads();
  for (int pass=0; pass<2; pass++) {
    float* arr = pass ? ac : ag;
    float mx = -1e30f;
    for (int t=tid;t<TT;t+=256) mx = fmaxf(mx, arr[t]);
    rbuf[tid]=mx; __syncthreads();
    for (int s=128;s>0;s>>=1){ if (tid<s) rbuf[tid]=fmaxf(rbuf[tid],rbuf[tid+s]); __syncthreads(); }
    mx = rbuf[0]; __syncthreads();
    float ls=0.f;
    for (int t=tid;t<TT;t+=256){ float e=expf(arr[t]-mx); arr[t]=e; ls+=e; }
    rbuf[tid]=ls; __syncthreads();
    for (int s=128;s>0;s>>=1){ if (tid<s) rbuf[tid]+=rbuf[tid+s]; __syncthreads(); }
    float inv = 1.0f/rbuf[0]; __syncthreads();
    for (int t=tid;t<TT;t+=256) arr[t]*=inv;
    __syncthreads();
  }
  for (int t=tid;t<TT;t+=256){ g_aligng[b*TT+t]=ag[t]; g_alignc[b*TT+t]=ac[t]; }
}

// ---------------- context = align_g @ enc_outs, T-sliced + atomic ----------------
__global__ void ctx_kernel(const float* __restrict__ enc) {
  int s = blockIdx.x;            // 0..9 (T slices of 60)
  int b = blockIdx.y;
  int tid = threadIdx.x;         // 512
  __shared__ float ag[60];
  if (tid < 60) ag[tid] = g_aligng[b*TT + s*60 + tid];
  __syncthreads();
  const float* eb = enc + (size_t)b*TT*HH + (size_t)(s*60)*HH + tid;
  float a0=0.f,a1=0.f,a2=0.f,a3=0.f,a4=0.f,a5=0.f;
  #pragma unroll 2
  for (int t=0;t<60;t+=6){
    a0 += ag[t]  *eb[(size_t)(t  )*HH];
    a1 += ag[t+1]*eb[(size_t)(t+1)*HH];
    a2 += ag[t+2]*eb[(size_t)(t+2)*HH];
    a3 += ag[t+3]*eb[(size_t)(t+3)*HH];
    a4 += ag[t+4]*eb[(size_t)(t+4)*HH];
    a5 += ag[t+5]*eb[(size_t)(t+5)*HH];
  }
  atomicAdd(&g_ctx[b*HH+tid], (a0+a1)+(a2+a3)+(a4+a5));
}

// ---------------- hidden_att finalize: tanh + switch ----------------
__global__ void ha_finalize_kernel(float* __restrict__ out_hidden,
                                   const float* __restrict__ Wf, const float* __restrict__ bf) {
  int b = blockIdx.x, tid = threadIdx.x;   // 512
  __shared__ float rb[512];
  float t = tanhf(g_ha[b*HH+tid]);
  out_hidden[b*HH+tid] = t;
  rb[tid] = t*Wf[tid];
  __syncthreads();
  for (int s=256;s>0;s>>=1){ if (tid<s) rb[tid]+=rb[tid+s]; __syncthreads(); }
  if (tid==0) g_switch[b] = sigf(rb[0]+bf[0]);
}

// ---------------- vocab softmax reductions ----------------
__global__ void vred_kernel() {
  int b = blockIdx.x, tid = threadIdx.x;   // 1024
  __shared__ float rb[1024];
  const float* lb = g_logits + (size_t)b*VV;
  float mx = -1e30f;
  for (int i=tid;i<VV;i+=1024) mx = fmaxf(mx, lb[i]);
  rb[tid]=mx; __syncthreads();
  for (int s=512;s>0;s>>=1){ if (tid<s) rb[tid]=fmaxf(rb[tid],rb[tid+s]); __syncthreads(); }
  mx = rb[0]; __syncthreads();
  float sm=0.f;
  for (int i=tid;i<VV;i+=1024) sm += expf(lb[i]-mx);
  rb[tid]=sm; __syncthreads();
  for (int s=512;s>0;s>>=1){ if (tid<s) rb[tid]+=rb[tid+s]; __syncthreads(); }
  if (tid==0){ g_vred[b*2]=mx; g_vred[b*2+1]=rb[0]; }
}

// ---------------- final: copy_prob stream + mix ----------------
__global__ void final_kernel(const float* __restrict__ enc_ins, float* __restrict__ result) {
  int b = blockIdx.y, tid = threadIdx.x;   // 256
  int v = blockIdx.x*256 + tid;
  __shared__ float ac[TT];
  for (int t=tid;t<TT;t+=256) ac[t]=g_alignc[b*TT+t];
  __syncthreads();
  if (v >= VV) return;
  const float* eb = enc_ins + (size_t)b*TT*VV + v;
  float a0=0.f,a1=0.f,a2=0.f,a3=0.f,a4=0.f,a5=0.f,a6=0.f,a7=0.f;
  for (int t=0;t<TT;t+=8){
    a0 += ac[t]  * eb[(size_t)(t  )*VV];
    a1 += ac[t+1]* eb[(size_t)(t+1)*VV];
    a2 += ac[t+2]* eb[(size_t)(t+2)*VV];
    a3 += ac[t+3]* eb[(size_t)(t+3)*VV];
    a4 += ac[t+4]* eb[(size_t)(t+4)*VV];
    a5 += ac[t+5]* eb[(size_t)(t+5)*VV];
    a6 += ac[t+6]* eb[(size_t)(t+6)*VV];
    a7 += ac[t+7]* eb[(size_t)(t+7)*VV];
  }
  float copy = ((a0+a1)+(a2+a3))+((a4+a5)+(a6+a7));
  float sw = g_switch[b];
  float mx = g_vred[b*2], sm = g_vred[b*2+1];
  float gen = expf(g_logits[(size_t)b*VV+v]-mx)/sm;
  result[(size_t)b*VV+v] = gen*(1.0f-sw) + copy*sw;
}

// ---------------- launch ----------------
extern "C" void kernel_launch(void* const* d_in, const int* in_sizes, int n_in,
                              void* d_out, int out_size) {
  const int*   x        = (const int*)  d_in[0];
  const float* lha      = (const float*)d_in[1];
  const float* h1       = (const float*)d_in[2];
  const float* c1       = (const float*)d_in[3];
  const float* h2       = (const float*)d_in[4];
  const float* c2       = (const float*)d_in[5];
  const float* enc_outs = (const float*)d_in[6];
  const float* enc_ins  = (const float*)d_in[7];
  const float* emb      = (const float*)d_in[8];
  const float* k1       = (const float*)d_in[9];
  const float* r1       = (const float*)d_in[10];
  const float* b1       = (const float*)d_in[11];
  const float* k2       = (const float*)d_in[12];
  const float* r2       = (const float*)d_in[13];
  const float* b2       = (const float*)d_in[14];
  const float* Wh       = (const float*)d_in[15];
  const float* bh       = (const float*)d_in[16];
  const float* Wg       = (const float*)d_in[17];
  const float* bg       = (const float*)d_in[18];
  const float* Wf       = (const float*)d_in[19];
  const float* bf       = (const float*)d_in[20];
  const float* aw1g     = (const float*)d_in[21];
  const float* aw2g     = (const float*)d_in[22];
  const float* avg      = (const float*)d_in[23];
  const float* aw1c     = (const float*)d_in[24];
  const float* aw2c     = (const float*)d_in[25];
  const float* avc      = (const float*)d_in[26];

  float* out = (float*)d_out;
  float* out_result = out;                       // 16*20000
  float* out_hidden = out + BB*VV;
  float* out_h1n    = out_hidden + BB*HH;
  float* out_c1n    = out_h1n + BB*HH;
  float* out_h2n    = out_c1n + BB*HH;
  float* out_c2n    = out_h2n + BB*HH;

  float *p_z1, *p_z2, *p_q, *p_ctx, *p_ha;
  cudaGetSymbolAddress((void**)&p_z1, g_z1);
  cudaGetSymbolAddress((void**)&p_z2, g_z2);
  cudaGetSymbolAddress((void**)&p_q, g_q);
  cudaGetSymbolAddress((void**)&p_ctx, g_ctx);
  cudaGetSymbolAddress((void**)&p_ha, g_ha);

  init_kernel<<<(98304+255)/256, 256>>>(b1, b2, bh);

  // Big independent GEMM: P = enc_outs @ [aw2g | aw2c]
  sgemm_attn_kernel<<<dim3(75,8), 256>>>(enc_outs, aw2g, aw2c);

  // LSTM 1: z1 += [emb, lha, h1] @ [k1; r1]
  GArgs az1; az1.A0=lha; az1.A1=h1; az1.W0=k1; az1.W1=r1;
  az1.xidx=x; az1.emb=emb; az1.C=p_z1; az1.K=1324; az1.N=2048;
  gemm16_atomic<V_Z1><<<dim3(16,21),128>>>(az1);
  lstm_pw_kernel<<<32,256>>>(p_z1, c1, out_h1n, out_c1n);

  // LSTM 2
  GArgs az2; az2.A0=out_h1n; az2.A1=h2; az2.W0=k2; az2.W1=r2;
  az2.xidx=nullptr; az2.emb=nullptr; az2.C=p_z2; az2.K=1024; az2.N=2048;
  gemm16_atomic<V_Z2><<<dim3(16,16),128>>>(az2);
  lstm_pw_kernel<<<32,256>>>(p_z2, c2, out_h2n, out_c2n);

  // queries (both heads)
  GArgs aq; aq.A0=out_h2n; aq.A1=nullptr; aq.W0=aw1g; aq.W1=aw1c;
  aq.xidx=nullptr; aq.emb=nullptr; aq.C=p_q; aq.K=512; aq.N=1024;
  gemm16_atomic<V_Q><<<dim3(8,8),128>>>(aq);

  scores_kernel<<<BT,256>>>(avg, avc);
  softmax_kernel<<<BB,256>>>();
  ctx_kernel<<<dim3(10,BB),512>>>(enc_outs);

  // hidden_att accum: g_ha += [ctx, h2n] @ Wh   (bias preloaded, tanh in finalize)
  GArgs aha; aha.A0=p_ctx; aha.A1=out_h2n; aha.W0=Wh; aha.W1=nullptr;
  aha.xidx=nullptr; aha.emb=nullptr; aha.C=p_ha; aha.K=1024; aha.N=512;
  gemm16_atomic<V_HA><<<dim3(4,16),128>>>(aha);
  ha_finalize_kernel<<<BB,512>>>(out_hidden, Wf, bf);

  gemm16_logits<<<(VV+127)/128,128>>>(out_hidden, Wg, bg);
  vred_kernel<<<BB,1024>>>();

  final_kernel<<<dim3((VV+255)/256, BB), 256>>>(enc_ins, out_result);
}